// round 14
// baseline (speedup 1.0000x reference)
#include <cuda_runtime.h>
#include <cuda_bf16.h>
#include <cstdint>

#define EMBED 1024
#define HEADS 16
#define HDIM  64
#define BATCH 2
#define SEQ   2048
#define MTOT  (BATCH*SEQ)   // 4096

using bf16 = __nv_bfloat16;

// ---------------- scratch (static device globals; allocation-free) ----------
__device__ bf16 g_Qhi[(size_t)BATCH*HEADS*SEQ*HDIM];   // [BH,S,D] bf16 hi/lo
__device__ bf16 g_Qlo[(size_t)BATCH*HEADS*SEQ*HDIM];
__device__ bf16 g_Khi[(size_t)BATCH*HEADS*SEQ*HDIM];
__device__ bf16 g_Klo[(size_t)BATCH*HEADS*SEQ*HDIM];
__device__ bf16 g_Vhi[(size_t)BATCH*HEADS*SEQ*HDIM];
__device__ bf16 g_Vlo[(size_t)BATCH*HEADS*SEQ*HDIM];

__device__ bf16 g_xhi[(size_t)MTOT*EMBED];
__device__ bf16 g_xlo[(size_t)MTOT*EMBED];
__device__ bf16 g_ahi[(size_t)MTOT*EMBED];            // attn out hi/lo (fused)
__device__ bf16 g_alo[(size_t)MTOT*EMBED];
__device__ bf16 g_Wthi[(size_t)4*EMBED*EMBED];        // W^T [N][K], 4 mats
__device__ bf16 g_Wtlo[(size_t)4*EMBED*EMBED];

// ---------------- PTX helpers (baseline sm_103 features only) ---------------
__device__ __forceinline__ uint32_t smem_u32(const void* p) {
    uint32_t a;
    asm("{ .reg .u64 t; cvta.to.shared.u64 t, %1; cvt.u32.u64 %0, t; }" : "=r"(a) : "l"(p));
    return a;
}
__device__ __forceinline__ void cp16(uint32_t s, const void* g) {
    asm volatile("cp.async.cg.shared.global [%0], [%1], 16;" :: "r"(s), "l"(g));
}
__device__ __forceinline__ void cp_commit() {
    asm volatile("cp.async.commit_group;" ::: "memory");
}
template<int N> __device__ __forceinline__ void cp_wait() {
    asm volatile("cp.async.wait_group %0;" :: "n"(N) : "memory");
}
__device__ __forceinline__ void ldsm4(uint32_t a, uint32_t& r0, uint32_t& r1,
                                      uint32_t& r2, uint32_t& r3) {
    asm volatile("ldmatrix.sync.aligned.m8n8.x4.shared.b16 {%0,%1,%2,%3}, [%4];"
                 : "=r"(r0), "=r"(r1), "=r"(r2), "=r"(r3) : "r"(a));
}
__device__ __forceinline__ void ldsm4t(uint32_t a, uint32_t& r0, uint32_t& r1,
                                       uint32_t& r2, uint32_t& r3) {
    asm volatile("ldmatrix.sync.aligned.m8n8.x4.trans.shared.b16 {%0,%1,%2,%3}, [%4];"
                 : "=r"(r0), "=r"(r1), "=r"(r2), "=r"(r3) : "r"(a));
}
__device__ __forceinline__ void mma16816(float* c, const uint32_t* a, const uint32_t* b) {
    asm volatile(
        "mma.sync.aligned.m16n8k16.row.col.f32.bf16.bf16.f32 "
        "{%0,%1,%2,%3}, {%4,%5,%6,%7}, {%8,%9}, {%0,%1,%2,%3};"
        : "+f"(c[0]), "+f"(c[1]), "+f"(c[2]), "+f"(c[3])
        : "r"(a[0]), "r"(a[1]), "r"(a[2]), "r"(a[3]), "r"(b[0]), "r"(b[1]));
}
// pack (e0,e1) -> bf16x2 hi + residual bf16x2 lo  (e0 in low half)
__device__ __forceinline__ void split2(float e0, float e1, uint32_t& hi, uint32_t& lo) {
    asm("cvt.rn.bf16x2.f32 %0, %1, %2;" : "=r"(hi) : "f"(e1), "f"(e0));
    float f0 = __uint_as_float(hi << 16);
    float f1 = __uint_as_float(hi & 0xFFFF0000u);
    float l0 = e0 - f0, l1 = e1 - f1;
    asm("cvt.rn.bf16x2.f32 %0, %1, %2;" : "=r"(lo) : "f"(l1), "f"(l0));
}

// ---------------- conversion kernels ---------------------------------------
__global__ void split_x(const float* __restrict__ in)
{
    int i = (blockIdx.x * blockDim.x + threadIdx.x) * 4;
    float4 v = *(const float4*)(in + i);
    uint32_t h0, l0, h1, l1;
    split2(v.x, v.y, h0, l0);
    split2(v.z, v.w, h1, l1);
    *(uint32_t*)(g_xhi + i)     = h0;
    *(uint32_t*)(g_xhi + i + 2) = h1;
    *(uint32_t*)(g_xlo + i)     = l0;
    *(uint32_t*)(g_xlo + i + 2) = l1;
}

// W [K][N] fp32 -> g_Wthi/g_Wtlo[z] [N][K] bf16 (transpose + hi/lo split); 4 mats via z
__global__ void transpose_split(const float* __restrict__ W0, const float* __restrict__ W1,
                                const float* __restrict__ W2, const float* __restrict__ W3)
{
    __shared__ float tile[32][33];
    const int widx = blockIdx.z;
    const float* W = (widx == 0) ? W0 : (widx == 1) ? W1 : (widx == 2) ? W2 : W3;
    bf16* Thi = g_Wthi + (size_t)widx * EMBED * EMBED;
    bf16* Tlo = g_Wtlo + (size_t)widx * EMBED * EMBED;
    const int bn = blockIdx.x * 32;
    const int bk = blockIdx.y * 32;
    const int tx = threadIdx.x, ty = threadIdx.y;   // (32, 8)
    #pragma unroll
    for (int i = 0; i < 4; i++)
        tile[ty + i * 8][tx] = W[(size_t)(bk + ty + i * 8) * EMBED + bn + tx];
    __syncthreads();
    #pragma unroll
    for (int i = 0; i < 4; i++) {
        float v = tile[tx][ty + i * 8];
        bf16 h = __float2bfloat16_rn(v);
        bf16 l = __float2bfloat16_rn(v - __bfloat162float(h));
        size_t off = (size_t)(bn + ty + i * 8) * EMBED + bk + tx;
        Thi[off] = h;
        Tlo[off] = l;
    }
}

// ---------------- mma.sync bf16 GEMM (hi/lo, 4-operand stages) ---------------
// C = (Ahi+Alo)@(Bhi+Blo)^T + bias  (drop lo*lo)
// CTA 256x128, BK=64, 8 warps (4m x 2n), warp tile 64x64.
// Per k-chunk: load Ahi,Alo,Bhi,Blo ONCE, run 3 mma passes in-register.
// 16 stages, double-buffered. QKV fused via blockIdx.z.
#define GROWB 144                     // padded row stride bytes (72 bf16)
#define GA_B  (256*GROWB)             // 36864 B per A operand
#define GB_B  (128*GROWB)             // 18432 B per B operand
#define GSTG  (2*GA_B + 2*GB_B)       // 110592 B per stage
#define GEMM_SMEM (2*GSTG + 512)      // 221696 B

__global__ void __launch_bounds__(256, 1)
mma_gemm(int asel, int widx0, int csel0,
         const float* __restrict__ bias0, const float* __restrict__ bias1,
         const float* __restrict__ bias2, float* __restrict__ Cext)
{
    extern __shared__ __align__(128) char smem[];
    float* bias_s = (float*)(smem + 2 * GSTG);
    const uint32_t sb = smem_u32(smem);

    const int z = blockIdx.z;
    const int widx = widx0 + z;
    const int csel = csel0 ? (csel0 + z) : 0;
    const float* bias = (z == 0) ? bias0 : (z == 1) ? bias1 : bias2;

    const bf16* Ahi = asel ? g_ahi : g_xhi;
    const bf16* Alo = asel ? g_alo : g_xlo;
    const bf16* Bthi = g_Wthi + (size_t)widx * EMBED * EMBED;
    const bf16* Btlo = g_Wtlo + (size_t)widx * EMBED * EMBED;

    const int tid = threadIdx.x, wid = tid >> 5, lane = tid & 31;
    const int bn = blockIdx.x * 128, bm = blockIdx.y * 256;
    const int wm = (wid >> 1) * 64, wn = (wid & 1) * 64;

    if (tid < 128) bias_s[tid] = bias[bn + tid];

    float acc[4][8][4];
    #pragma unroll
    for (int mi = 0; mi < 4; mi++)
        #pragma unroll
        for (int ni = 0; ni < 8; ni++)
            #pragma unroll
            for (int c = 0; c < 4; c++) acc[mi][ni][c] = 0.f;

    // stage s covers k-chunk [s*64, s*64+64); loads all 4 operand tiles
    auto load_stage = [&](int s) {
        const int koff = s * 64;
        const uint32_t base = sb + (s & 1) * GSTG;
        // A operands: 256 rows x 8 c8 each -> 2048 cp16 each -> 8/thread each
        #pragma unroll
        for (int i = 0; i < 8; i++) {
            int idx = tid + i * 256;
            int row = idx >> 3, c8 = idx & 7;
            const size_t goff = (size_t)(bm + row) * EMBED + koff + c8 * 8;
            uint32_t soff = row * GROWB + c8 * 16;
            cp16(base + soff, Ahi + goff);
            cp16(base + GA_B + soff, Alo + goff);
        }
        // B operands: 128 rows x 8 c8 -> 1024 cp16 each -> 4/thread each
        #pragma unroll
        for (int i = 0; i < 4; i++) {
            int idx = tid + i * 256;
            int row = idx >> 3, c8 = idx & 7;
            const size_t goff = (size_t)(bn + row) * EMBED + koff + c8 * 8;
            uint32_t soff = row * GROWB + c8 * 16;
            cp16(base + 2 * GA_B + soff, Bthi + goff);
            cp16(base + 2 * GA_B + GB_B + soff, Btlo + goff);
        }
        cp_commit();
    };

    load_stage(0);

    for (int s = 0; s < 16; s++) {
        if (s + 1 < 16) { load_stage(s + 1); cp_wait<1>(); }
        else            { cp_wait<0>(); }
        __syncthreads();

        const uint32_t sAhi = sb + (s & 1) * GSTG;
        const uint32_t sAlo = sAhi + GA_B;
        const uint32_t sBhi = sAhi + 2 * GA_B;
        const uint32_t sBlo = sBhi + GB_B;

        #pragma unroll
        for (int k = 0; k < 64; k += 16) {
            uint32_t af[4][4], bh[4][4], bl[4][4];
            const uint32_t arow = (lane & 15);
            const uint32_t aoff = k * 2 + (lane >> 4) * 16;
            const uint32_t brow = (lane & 7) + (lane >> 4) * 8;
            const uint32_t boff = k * 2 + ((lane >> 3) & 1) * 16;
            #pragma unroll
            for (int mi = 0; mi < 4; mi++)
                ldsm4(sAhi + (wm + mi * 16 + arow) * GROWB + aoff,
                      af[mi][0], af[mi][1], af[mi][2], af[mi][3]);
            #pragma unroll
            for (int nb = 0; nb < 4; nb++)
                ldsm4(sBhi + (wn + nb * 16 + brow) * GROWB + boff,
                      bh[nb][0], bh[nb][1], bh[nb][2], bh[nb][3]);
            #pragma unroll
            for (int nb = 0; nb < 4; nb++)
                ldsm4(sBlo + (wn + nb * 16 + brow) * GROWB + boff,
                      bl[nb][0], bl[nb][1], bl[nb][2], bl[nb][3]);
            // pass 0: Ahi x Bhi
            #pragma unroll
            for (int mi = 0; mi < 4; mi++)
                #pragma unroll
                for (int nb = 0; nb < 4; nb++) {
                    mma16816(acc[mi][2*nb],   af[mi], &bh[nb][0]);
                    mma16816(acc[mi][2*nb+1], af[mi], &bh[nb][2]);
                }
            // pass 1: Ahi x Blo
            #pragma unroll
            for (int mi = 0; mi < 4; mi++)
                #pragma unroll
                for (int nb = 0; nb < 4; nb++) {
                    mma16816(acc[mi][2*nb],   af[mi], &bl[nb][0]);
                    mma16816(acc[mi][2*nb+1], af[mi], &bl[nb][2]);
                }
            // pass 2: Alo x Bhi  (reload A frags as lo)
            #pragma unroll
            for (int mi = 0; mi < 4; mi++)
                ldsm4(sAlo + (wm + mi * 16 + arow) * GROWB + aoff,
                      af[mi][0], af[mi][1], af[mi][2], af[mi][3]);
            #pragma unroll
            for (int mi = 0; mi < 4; mi++)
                #pragma unroll
                for (int nb = 0; nb < 4; nb++) {
                    mma16816(acc[mi][2*nb],   af[mi], &bh[nb][0]);
                    mma16816(acc[mi][2*nb+1], af[mi], &bh[nb][2]);
                }
        }
        __syncthreads();
    }

    const int lr = lane >> 2, lc = (lane & 3) * 2;
    if (csel != 0) {
        bf16 *Chi, *Clo;
        if (csel == 1)      { Chi = g_Qhi; Clo = g_Qlo; }
        else if (csel == 2) { Chi = g_Khi; Clo = g_Klo; }
        else                { Chi = g_Vhi; Clo = g_Vlo; }
        #pragma unroll
        for (int mi = 0; mi < 4; mi++) {
            #pragma unroll
            for (int ni = 0; ni < 8; ni++) {
                const int col = bn + wn + ni * 8 + lc;
                const float b0 = bias_s[wn + ni * 8 + lc];
                const float b1 = bias_s[wn + ni * 8 + lc + 1];
                const int h = col >> 6, d = col & 63;
                #pragma unroll
                for (int half = 0; half < 2; half++) {
                    const int m = bm + wm + mi * 16 + lr + half * 8;
                    const int bb = m >> 11, sq = m & (SEQ - 1);
                    uint32_t hi2, lo2;
                    split2(acc[mi][ni][half * 2 + 0] + b0,
                           acc[mi][ni][half * 2 + 1] + b1, hi2, lo2);
                    size_t off = (((size_t)(bb * HEADS + h) * SEQ) + sq) * HDIM + d;
                    *(uint32_t*)(Chi + off) = hi2;
                    *(uint32_t*)(Clo + off) = lo2;
                }
            }
        }
    } else {
        #pragma unroll
        for (int mi = 0; mi < 4; mi++) {
            #pragma unroll
            for (int ni = 0; ni < 8; ni++) {
                const int col = bn + wn + ni * 8 + lc;
                const float b0 = bias_s[wn + ni * 8 + lc];
                const float b1 = bias_s[wn + ni * 8 + lc + 1];
                #pragma unroll
                for (int half = 0; half < 2; half++) {
                    const int m = bm + wm + mi * 16 + lr + half * 8;
                    float2 v;
                    v.x = acc[mi][ni][half * 2 + 0] + b0;
                    v.y = acc[mi][ni][half * 2 + 1] + b1;
                    *(float2*)(Cext + (size_t)m * EMBED + col) = v;
                }
            }
        }
    }
}

// ---------------------------------------------------------------------------
// Tensor-core flash attention (unchanged — proven).
// ---------------------------------------------------------------------------
#define ROWB  144
#define QSZ   (128*ROWB)
#define KVARR (64*ROWB)
#define KVSTG (4*KVARR)
#define ATTN_SMEM (2*QSZ + 2*KVSTG)

__global__ void __launch_bounds__(256)
attn_mma()
{
    extern __shared__ __align__(128) char smem[];
    const uint32_t uQ  = smem_u32(smem);
    const uint32_t uKV = uQ + 2 * QSZ;

    const int tid = threadIdx.x;
    const int w = tid >> 5, lane = tid & 31;
    const int qt = blockIdx.x;
    const int bh = blockIdx.y;
    const int b = bh >> 4, h = bh & 15;

    const bf16* gQh = g_Qhi + ((size_t)bh * SEQ + qt * 128) * HDIM;
    const bf16* gQl = g_Qlo + ((size_t)bh * SEQ + qt * 128) * HDIM;
    const bf16* gKh = g_Khi + (size_t)bh * SEQ * HDIM;
    const bf16* gKl = g_Klo + (size_t)bh * SEQ * HDIM;
    const bf16* gVh = g_Vhi + (size_t)bh * SEQ * HDIM;
    const bf16* gVl = g_Vlo + (size_t)bh * SEQ * HDIM;

    #pragma unroll
    for (int i = 0; i < 8; i++) {
        int c = tid + i * 256;
        int arr = c >> 10, rem = c & 1023;
        int row = rem >> 3, c8 = rem & 7;
        const bf16* g = (arr ? gQl : gQh) + row * HDIM + c8 * 8;
        cp16(uQ + arr * QSZ + row * ROWB + c8 * 16, g);
    }
    cp_commit();

    auto load_kv = [&](int kt, int buf) {
        #pragma unroll
        for (int i = 0; i < 8; i++) {
            int c = tid + i * 256;
            int arr = c >> 9, rem = c & 511;
            int row = rem >> 3, c8 = rem & 7;
            const bf16* g = (arr < 2) ? (arr ? gKl : gKh) : ((arr == 2) ? gVh : gVl);
            cp16(uKV + buf * KVSTG + arr * KVARR + row * ROWB + c8 * 16,
                 g + (size_t)(kt * 64 + row) * HDIM + c8 * 8);
        }
        cp_commit();
    };

    load_kv(0, 0);
    cp_wait<1>();
    __syncthreads();

    uint32_t qh[4][4], ql[4][4];
    #pragma unroll
    for (int kb = 0; kb < 4; kb++) {
        uint32_t a = uQ + (w * 16 + (lane & 15)) * ROWB + kb * 32 + (lane >> 4) * 16;
        ldsm4(a, qh[kb][0], qh[kb][1], qh[kb][2], qh[kb][3]);
        ldsm4(a + QSZ, ql[kb][0], ql[kb][1], ql[kb][2], ql[kb][3]);
    }

    float o[8][4];
    #pragma unroll
    for (int ni = 0; ni < 8; ni++)
        #pragma unroll
        for (int c = 0; c < 4; c++) o[ni][c] = 0.f;
    float mrow[2] = { -1e30f, -1e30f };
    float lrow[2] = { 0.f, 0.f };

    for (int kt = 0; kt < SEQ / 64; kt++) {
        const int buf = kt & 1;
        __syncthreads();
        if (kt + 1 < SEQ / 64) { load_kv(kt + 1, buf ^ 1); cp_wait<1>(); }
        else                   { cp_wait<0>(); }
        __syncthreads();

        const uint32_t kHi = uKV + buf * KVSTG;
        const uint32_t kLo = kHi + KVARR;
        const uint32_t vHi = kHi + 2 * KVARR;
        const uint32_t vLo = kHi + 3 * KVARR;

        float s[8][4];
        #pragma unroll
        for (int ni = 0; ni < 8; ni++)
            #pragma unroll
            for (int c = 0; c < 4; c++) s[ni][c] = 0.f;

        #pragma unroll
        for (int kb = 0; kb < 4; kb++) {
            uint32_t bk[4][4];
            const uint32_t nofs = (lane & 7) + (lane >> 4) * 8;
            const uint32_t kofs = kb * 32 + ((lane >> 3) & 1) * 16;
            #pragma unroll
            for (int nb = 0; nb < 4; nb++)
                ldsm4(kHi + (nb * 16 + nofs) * ROWB + kofs,
                      bk[nb][0], bk[nb][1], bk[nb][2], bk[nb][3]);
            #pragma unroll
            for (int nb = 0; nb < 4; nb++) {
                mma16816(s[2*nb],   qh[kb], &bk[nb][0]);
                mma16816(s[2*nb+1], qh[kb], &bk[nb][2]);
                mma16816(s[2*nb],   ql[kb], &bk[nb][0]);
                mma16816(s[2*nb+1], ql[kb], &bk[nb][2]);
            }
            #pragma unroll
            for (int nb = 0; nb < 4; nb++)
                ldsm4(kLo + (nb * 16 + nofs) * ROWB + kofs,
                      bk[nb][0], bk[nb][1], bk[nb][2], bk[nb][3]);
            #pragma unroll
            for (int nb = 0; nb < 4; nb++) {
                mma16816(s[2*nb],   qh[kb], &bk[nb][0]);
                mma16816(s[2*nb+1], qh[kb], &bk[nb][2]);
            }
        }

        #pragma unroll
        for (int ni = 0; ni < 8; ni++)
            #pragma unroll
            for (int c = 0; c < 4; c++) s[ni][c] *= 0.125f;

        #pragma unroll
        for (int hf = 0; hf < 2; hf++) {
            float rm = s[0][2*hf];
            #pragma unroll
            for (int ni = 0; ni < 8; ni++) {
                rm = fmaxf(rm, s[ni][2*hf]);
                rm = fmaxf(rm, s[ni][2*hf+1]);
            }
            rm = fmaxf(rm, __shfl_xor_sync(0xffffffffu, rm, 1));
            rm = fmaxf(rm, __shfl_xor_sync(0xffffffffu, rm, 2));
            const float mnew = fmaxf(mrow[hf], rm);
            const float corr = __expf(mrow[hf] - mnew);
            mrow[hf] = mnew;
            float rs = 0.f;
            #pragma unroll
            for (int ni = 0; ni < 8; ni++) {
                float p0 = __expf(s[ni][2*hf]   - mnew);
                float p1 = __expf(s[ni][2*hf+1] - mnew);
                s[ni][2*hf] = p0; s[ni][2*hf+1] = p1;
                rs += p0 + p1;
            }
            rs += __shfl_xor_sync(0xffffffffu, rs, 1);
            rs += __shfl_xor_sync(0xffffffffu, rs, 2);
            lrow[hf] = lrow[hf] * corr + rs;
            #pragma unroll
            for (int ni = 0; ni < 8; ni++) {
                o[ni][2*hf]   *= corr;
                o[ni][2*hf+1] *= corr;
            }
        }

        uint32_t ph[4][4], pl[4][4];
        #pragma unroll
        for (int kb = 0; kb < 4; kb++) {
            split2(s[2*kb][0],   s[2*kb][1],   ph[kb][0], pl[kb][0]);
            split2(s[2*kb][2],   s[2*kb][3],   ph[kb][1], pl[kb][1]);
            split2(s[2*kb+1][0], s[2*kb+1][1], ph[kb][2], pl[kb][2]);
            split2(s[2*kb+1][2], s[2*kb+1][3], ph[kb][3], pl[kb][3]);
        }

        #pragma unroll
        for (int kb = 0; kb < 4; kb++) {
            uint32_t bv[4][4];
            const uint32_t krow = kb * 16 + (lane & 7) + ((lane >> 3) & 1) * 8;
            const uint32_t ncol = (lane >> 4) * 16;
            #pragma unroll
            for (int nb = 0; nb < 4; nb++)
                ldsm4t(vHi + krow * ROWB + nb * 32 + ncol,
                       bv[nb][0], bv[nb][1], bv[nb][2], bv[nb][3]);
            #pragma unroll
            for (int nb = 0; nb < 4; nb++) {
                mma16816(o[2*nb],   ph[kb], &bv[nb][0]);
                mma16816(o[2*nb+1], ph[kb], &bv[nb][2]);
                mma16816(o[2*nb],   pl[kb], &bv[nb][0]);
                mma16816(o[2*nb+1], pl[kb], &bv[nb][2]);
            }
            #pragma unroll
            for (int nb = 0; nb < 4; nb++)
                ldsm4t(vLo + krow * ROWB + nb * 32 + ncol,
                       bv[nb][0], bv[nb][1], bv[nb][2], bv[nb][3]);
            #pragma unroll
            for (int nb = 0; nb < 4; nb++) {
                mma16816(o[2*nb],   ph[kb], &bv[nb][0]);
                mma16816(o[2*nb+1], ph[kb], &bv[nb][2]);
            }
        }
    }

    const float inv0 = 1.f / lrow[0];
    const float inv1 = 1.f / lrow[1];
    const int lr = lane >> 2, lc = (lane & 3) * 2;
    const size_t r0 = ((size_t)b * SEQ + qt * 128 + w * 16 + lr) * EMBED + h * 64;
    const size_t r1 = r0 + (size_t)8 * EMBED;
    #pragma unroll
    for (int ni = 0; ni < 8; ni++) {
        const int d = ni * 8 + lc;
        uint32_t hi2, lo2;
        split2(o[ni][0] * inv0, o[ni][1] * inv0, hi2, lo2);
        *(uint32_t*)(g_ahi + r0 + d) = hi2;
        *(uint32_t*)(g_alo + r0 + d) = lo2;
        split2(o[ni][2] * inv1, o[ni][3] * inv1, hi2, lo2);
        *(uint32_t*)(g_ahi + r1 + d) = hi2;
        *(uint32_t*)(g_alo + r1 + d) = lo2;
    }
}

// ---------------------------------------------------------------------------
extern "C" void kernel_launch(void* const* d_in, const int* in_sizes, int n_in,
                              void* d_out, int out_size)
{
    const float* x  = (const float*)d_in[0];
    const float* Wq = (const float*)d_in[1];
    const float* bq = (const float*)d_in[2];
    const float* Wk = (const float*)d_in[3];
    const float* bk = (const float*)d_in[4];
    const float* Wv = (const float*)d_in[5];
    const float* bv = (const float*)d_in[6];
    const float* Wo = (const float*)d_in[7];
    const float* bo = (const float*)d_in[8];
    float* out = (float*)d_out;

    cudaFuncSetAttribute(mma_gemm, cudaFuncAttributeMaxDynamicSharedMemorySize, GEMM_SMEM);
    cudaFuncSetAttribute(attn_mma, cudaFuncAttributeMaxDynamicSharedMemorySize, ATTN_SMEM);

    const int NTOT = MTOT * EMBED;
    split_x<<<NTOT / 4 / 256, 256>>>(x);

    transpose_split<<<dim3(EMBED / 32, EMBED / 32, 4), dim3(32, 8)>>>(Wq, Wk, Wv, Wo);

    // fused QKV projections: blockIdx.z = 0,1,2 -> Q,K,V
    mma_gemm<<<dim3(EMBED / 128, MTOT / 256, 3), 256, GEMM_SMEM>>>(
        0, 0, 1, bq, bk, bv, nullptr);

    attn_mma<<<dim3(SEQ / 128, BATCH * HEADS), 256, ATTN_SMEM>>>();

    mma_gemm<<<dim3(EMBED / 128, MTOT / 256, 1), 256, GEMM_SMEM>>>(
        1, 3, 0, bo, nullptr, nullptr, out);
}